// round 12
// baseline (speedup 1.0000x reference)
#include <cuda_runtime.h>
#include <cuda_fp16.h>
#include <cstdint>

#define T_STEPS 512
#define BATCH   128
#define IDIM    512
#define HDIM    512
#define BH      (BATCH * HDIM)   /* 65536 */
#define XB      (BATCH * IDIM)   /* x slab stride per timestep, floats */

__device__ __forceinline__ uint32_t pack_h2(float a, float b) {
    __half2 h = __floats2half2_rn(a, b);
    return *reinterpret_cast<uint32_t*>(&h);
}
__device__ __forceinline__ float tanh_fast(float x) {
    float e = __expf(2.0f * x);
    return 1.0f - __fdividef(2.0f, e + 1.0f);
}
__device__ __forceinline__ void mma_f16(float c[4], const uint32_t a[4],
                                        uint32_t b0, uint32_t b1) {
    asm volatile(
        "mma.sync.aligned.m16n8k16.row.col.f32.f16.f16.f32 "
        "{%0,%1,%2,%3}, {%4,%5,%6,%7}, {%8,%9}, {%0,%1,%2,%3};"
        : "+f"(c[0]), "+f"(c[1]), "+f"(c[2]), "+f"(c[3])
        : "r"(a[0]), "r"(a[1]), "r"(a[2]), "r"(a[3]), "r"(b0), "r"(b1));
}
__device__ __forceinline__ uint32_t smem_u32(const void* p) {
    return (uint32_t)__cvta_generic_to_shared(p);
}
__device__ __forceinline__ uint32_t mapa_rank(uint32_t addr, uint32_t rank) {
    uint32_t r;
    asm("mapa.shared::cluster.u32 %0, %1, %2;" : "=r"(r) : "r"(addr), "r"(rank));
    return r;
}
__device__ __forceinline__ void st_cluster_u32(uint32_t addr, uint32_t v) {
    asm volatile("st.shared::cluster.u32 [%0], %1;" :: "r"(addr), "r"(v) : "memory");
}

// ============================================================================
// FUSED kernel: xw GEMM + recurrence in ONE persistent clustered kernel.
// 16 clusters x 8 CTAs; CTA (j,i): batch rows j*8..+7, H cols i*64..+63.
// Per step t:
//   [t>0] cluster.wait -> rec MMA (W_hh frags, Hs) -> Red reduce -> s
//   r = tanh(xw_t + s)   (xw_t computed LAST step in the barrier slack)
//   push fp16x2 h_t to 8 ranks -> cluster.arrive -> STG out[t]
//   xw pipeline for t+1: STS-stage x[t+1] (LDG'd a step earlier) -> bar ->
//     xw MMA (W_ih frags) -> Red reduce -> bar -> xwv = sum + bias
//     (LDG x[t+2] issued right after staging; full step to complete)
// Sync skeleton (arrive/wait counts, push, buffers) identical to proven R8.
// ============================================================================
__global__ __launch_bounds__(256) __cluster_dims__(8, 1, 1)
void rnn_fused_kernel(const float* __restrict__ x,
                      const float* __restrict__ w_ih,
                      const float* __restrict__ w_hh,
                      const float* __restrict__ bias,
                      float* __restrict__ out) {
    __shared__ uint32_t Hs[2][8][256];              // 16 KB  h exchange (fp16x2)
    __shared__ uint32_t Xst[8][256];                // 8 KB   x staging (fp16x2)
    __shared__ __align__(16) float Red[8][544];     // 17 KB  reduce, pitch 68

    const int tid  = threadIdx.x;
    const int warp = tid >> 5, lane = tid & 31;
    const int g = lane >> 2, tg = lane & 3;
    const int j = blockIdx.x >> 3;   // batch group 0..15
    const int i = blockIdx.x & 7;    // rank == n slice 0..7

    // ---- W_hh and W_ih slices as fp16 m16n8k16 A-fragments (64+64 regs) ----
    uint32_t aw[4][4][4], awx[4][4][4];
#pragma unroll
    for (int nb = 0; nb < 4; nb++)
#pragma unroll
        for (int k16 = 0; k16 < 4; k16++) {
            const int r0w = i * 64 + nb * 16 + g;
            const int r1w = r0w + 8;
            const int col = warp * 64 + k16 * 16 + tg * 2;
            const float* w0 = w_hh + (size_t)r0w * HDIM + col;
            const float* w1 = w_hh + (size_t)r1w * HDIM + col;
            aw[nb][k16][0] = pack_h2(w0[0], w0[1]);
            aw[nb][k16][1] = pack_h2(w1[0], w1[1]);
            aw[nb][k16][2] = pack_h2(w0[8], w0[9]);
            aw[nb][k16][3] = pack_h2(w1[8], w1[9]);
            const float* v0 = w_ih + (size_t)r0w * IDIM + col;
            const float* v1 = w_ih + (size_t)r1w * IDIM + col;
            awx[nb][k16][0] = pack_h2(v0[0], v0[1]);
            awx[nb][k16][1] = pack_h2(v1[0], v1[1]);
            awx[nb][k16][2] = pack_h2(v0[8], v0[9]);
            awx[nb][k16][3] = pack_h2(v1[8], v1[9]);
        }

    // Ownership: thread -> (batch row m = warp, H cols i*64 + lane*2, +1)
    const int m = warp;
    const int n = lane * 2;
    const size_t obase = (size_t)(j * 8 + m) * HDIM + i * 64 + n;
    const float bb0 = bias[i * 64 + n];
    const float bb1 = bias[i * 64 + n + 1];

    const uint32_t hs_word = (uint32_t)(m * 256 + ((i * 32 + lane) ^ (m * 4)));
    const uint32_t hs_addr0 = smem_u32(&Hs[0][0][0]) + hs_word * 4;
    uint32_t hpush[8];
#pragma unroll
    for (int r = 0; r < 8; r++) hpush[r] = mapa_rank(hs_addr0, (i + r) & 7);

    // this warp owns batch row (j*8 + warp) of each x[t] slab
    const float* xrow_base = x + ((size_t)j * 8 + warp) * IDIM;

    asm volatile("barrier.cluster.arrive.aligned;" ::: "memory");
    asm volatile("barrier.cluster.wait.aligned;" ::: "memory");

    // ---- prologue: compute xw[0]; prefetch x[1] ----
    float2 xr[8];
#pragma unroll
    for (int k = 0; k < 8; k++)
        xr[k] = *(const float2*)(xrow_base + (lane + 32 * k) * 2);
#pragma unroll
    for (int k = 0; k < 8; k++)
        Xst[warp][(lane + 32 * k) ^ (warp * 4)] = pack_h2(xr[k].x, xr[k].y);
    __syncthreads();

    float2 xwv;
    {
        float cx[4][4] = {};
#pragma unroll
        for (int k16 = 0; k16 < 4; k16++) {
            const int base = warp * 32 + k16 * 8;
            uint32_t b0 = Xst[g][(base + tg) ^ (g * 4)];
            uint32_t b1 = Xst[g][(base + tg + 4) ^ (g * 4)];
#pragma unroll
            for (int nb = 0; nb < 4; nb++)
                mma_f16(cx[nb], awx[nb][k16], b0, b1);
        }
        float* rp = Red[warp];
#pragma unroll
        for (int nb = 0; nb < 4; nb++)
#pragma unroll
            for (int r = 0; r < 4; r++) {
                int idx = (tg * 2 + (r & 1)) * 68 + nb * 16 + g + ((r & 2) << 2);
                rp[idx] = cx[nb][r];
            }
        __syncthreads();
        float s0 = 0.f, s1 = 0.f;
#pragma unroll
        for (int w = 0; w < 8; w++) {
            float2 v = *(const float2*)&Red[w][m * 68 + n];
            s0 += v.x; s1 += v.y;
        }
        xwv = make_float2(s0 + bb0, s1 + bb1);
    }
#pragma unroll
    for (int k = 0; k < 8; k++)
        xr[k] = *(const float2*)(xrow_base + (size_t)XB + (lane + 32 * k) * 2);

    for (int t = 0; t < T_STEPS; t++) {
        float r0, r1;
        if (t == 0) {
            r0 = tanh_fast(xwv.x);
            r1 = tanh_fast(xwv.y);
        } else {
            asm volatile("barrier.cluster.wait.aligned;" ::: "memory");
            const uint32_t* hb = &Hs[(t + 1) & 1][0][0];

            float c[4][4] = {};
#pragma unroll
            for (int k16 = 0; k16 < 4; k16++) {
                const int base = warp * 32 + k16 * 8;
                uint32_t b0 = hb[g * 256 + ((base + tg) ^ (g * 4))];
                uint32_t b1 = hb[g * 256 + ((base + tg + 4) ^ (g * 4))];
#pragma unroll
                for (int nb = 0; nb < 4; nb++)
                    mma_f16(c[nb], aw[nb][k16], b0, b1);
            }
            float* rp = Red[warp];
#pragma unroll
            for (int nb = 0; nb < 4; nb++)
#pragma unroll
                for (int r = 0; r < 4; r++) {
                    int idx = (tg * 2 + (r & 1)) * 68 + nb * 16 + g + ((r & 2) << 2);
                    rp[idx] = c[nb][r];
                }
            __syncthreads();
            float s0 = 0.f, s1 = 0.f;
#pragma unroll
            for (int w = 0; w < 8; w++) {
                float2 v = *(const float2*)&Red[w][m * 68 + n];
                s0 += v.x; s1 += v.y;
            }
            r0 = tanh_fast(xwv.x + s0);
            r1 = tanh_fast(xwv.y + s1);
        }

        if (t < T_STEPS - 1) {
            const uint32_t pv = pack_h2(r0, r1);
            const uint32_t boff = (t & 1) ? 8192u : 0u;
#pragma unroll
            for (int r = 0; r < 8; r++) st_cluster_u32(hpush[r] + boff, pv);
            asm volatile("barrier.cluster.arrive.aligned;" ::: "memory");
        }

        *(float2*)(out + (size_t)t * BH + obase) = make_float2(r0, r1);

        if (t == T_STEPS - 1) {
            *(float2*)(out + (size_t)T_STEPS * BH + obase) = make_float2(r0, r1);
        } else {
            // ---- xw pipeline for t+1, in the cluster-barrier slack ----
#pragma unroll
            for (int k = 0; k < 8; k++)
                Xst[warp][(lane + 32 * k) ^ (warp * 4)] = pack_h2(xr[k].x, xr[k].y);
            __syncthreads();
            if (t + 2 < T_STEPS) {   // prefetch x[t+2]; consumed next step
                const float* xp = xrow_base + (size_t)(t + 2) * XB;
#pragma unroll
                for (int k = 0; k < 8; k++)
                    xr[k] = *(const float2*)(xp + (lane + 32 * k) * 2);
            }
            float cx[4][4] = {};
#pragma unroll
            for (int k16 = 0; k16 < 4; k16++) {
                const int base = warp * 32 + k16 * 8;
                uint32_t b0 = Xst[g][(base + tg) ^ (g * 4)];
                uint32_t b1 = Xst[g][(base + tg + 4) ^ (g * 4)];
#pragma unroll
                for (int nb = 0; nb < 4; nb++)
                    mma_f16(cx[nb], awx[nb][k16], b0, b1);
            }
            float* rp = Red[warp];
#pragma unroll
            for (int nb = 0; nb < 4; nb++)
#pragma unroll
                for (int r = 0; r < 4; r++) {
                    int idx = (tg * 2 + (r & 1)) * 68 + nb * 16 + g + ((r & 2) << 2);
                    rp[idx] = cx[nb][r];
                }
            __syncthreads();
            float s0 = 0.f, s1 = 0.f;
#pragma unroll
            for (int w = 0; w < 8; w++) {
                float2 v = *(const float2*)&Red[w][m * 68 + n];
                s0 += v.x; s1 += v.y;
            }
            xwv = make_float2(s0 + bb0, s1 + bb1);
        }
    }

    asm volatile("barrier.cluster.arrive.aligned;" ::: "memory");
    asm volatile("barrier.cluster.wait.aligned;" ::: "memory");
}

extern "C" void kernel_launch(void* const* d_in, const int* in_sizes, int n_in,
                              void* d_out, int out_size) {
    (void)in_sizes; (void)n_in; (void)out_size;
    const float* x    = (const float*)d_in[0];
    const float* w_ih = (const float*)d_in[1];
    const float* w_hh = (const float*)d_in[2];
    const float* b    = (const float*)d_in[3];
    float* out = (float*)d_out;

    // single fused persistent kernel: 16 clusters x 8 CTAs
    rnn_fused_kernel<<<128, 256>>>(x, w_ih, w_hh, b, out);
}